// round 10
// baseline (speedup 1.0000x reference)
#include <cuda_runtime.h>
#include <cuda_fp16.h>
#include <cstdint>

// ---------------------------------------------------------------------------
// PivNet fused MLP, GB300 sm_103a.
// B=524288, DIM=4, GRID=16, K=100, H=512, FEAT=105 (padded to 128 in layer 1).
// Per CTA: 64 rows. Activations fp16 in smem; full-layer fp32 accumulators in
// registers; weights pre-split fp16 hi+lo (x1024) streamed via cp.async.
// GEMM core: mma.sync.aligned.m16n8k16.row.col.f32.f16.f16.f32
// ---------------------------------------------------------------------------

#define NPIECE     103          // 7 (L1) + 32 (L2) + 32 (L3) + 32 (L4)
#define NBIG       71           // pieces with N=512 (L1..L3)
#define PIECE_BIG  16384        // halves: 16k x 512n x 2 (hi+lo)
#define PIECE_SML  4096         // halves: 16k x 128n x 2 (L4)

// smem layout (in halves):
//   A     [64][520]          @ 0       (66560 B)
//   Wbuf  2 x 16384          @ 33280   (65536 B)
//   bias  1664 floats        @ 66048   ( 6656 B)
#define SMEM_BYTES 139264

__device__ __align__(16) __half g_wp[NBIG * PIECE_BIG + 32 * PIECE_SML];

__host__ __device__ __forceinline__ int piece_off(int p) {
    return p < NBIG ? p * PIECE_BIG : NBIG * PIECE_BIG + (p - NBIG) * PIECE_SML;
}

// swizzled half index within one hi/lo block: rows of 16 halves (k16),
// 4-byte words permuted by n bit2 -> conflict-free b-fragment LDS.
__host__ __device__ __forceinline__ int bswz(int n, int k) {
    int w = (k >> 1) ^ (((n >> 2) & 1) << 2);
    return n * 16 + w * 2 + (k & 1);
}

// ---------------- weight prep: fp32 -> swizzled fp16 hi/lo pieces ----------
__global__ void prep_weights(const float* __restrict__ W1, const float* __restrict__ W2,
                             const float* __restrict__ W3, const float* __restrict__ W4)
{
    int t = blockIdx.x * blockDim.x + threadIdx.x;
    if (t >= NPIECE * 8192) return;
    int p = t >> 13, rem = t & 8191;
    int n = rem >> 4, k = rem & 15;
    const float* W; int Kd, Nd, ld, k16;
    if (p < 7)       { W = W1; Kd = 105; Nd = 512; ld = 512; k16 = p;      }
    else if (p < 39) { W = W2; Kd = 512; Nd = 512; ld = 512; k16 = p - 7;  }
    else if (p < 71) { W = W3; Kd = 512; Nd = 512; ld = 512; k16 = p - 39; }
    else             { W = W4; Kd = 512; Nd = 100; ld = 100; k16 = p - 71;
                       if (n >= 128) return; }
    int Nn = (p < NBIG) ? 512 : 128;
    int gk = k16 * 16 + k;
    float w = 0.0f;
    if (gk < Kd && n < Nd) w = W[(size_t)gk * ld + n] * 1024.0f;  // scale keeps lo normal
    __half hi = __float2half_rn(w);
    __half lo = __float2half_rn(w - __half2float(hi));
    int base = piece_off(p), i = bswz(n, k);
    g_wp[base + i]           = hi;
    g_wp[base + Nn * 16 + i] = lo;
}

__device__ __forceinline__ void cp16(void* dst, const void* src) {
    uint32_t d = (uint32_t)__cvta_generic_to_shared(dst);
    asm volatile("cp.async.cg.shared.global [%0], [%1], 16;" :: "r"(d), "l"(src) : "memory");
}

// ---------------- main fused kernel ----------------------------------------
__global__ void __launch_bounds__(256, 1)
pivnet_main(const float* __restrict__ x,  const float* __restrict__ mnv,
            const float* __restrict__ mxv, const float* __restrict__ pivots,
            const float* __restrict__ knnd, const float* __restrict__ qm,
            const float* __restrict__ qs,  const float* __restrict__ km,
            const float* __restrict__ ks,  const float* __restrict__ b1,
            const float* __restrict__ b2,  const float* __restrict__ b3,
            const float* __restrict__ b4,  float* __restrict__ out)
{
    extern __shared__ __half smem[];
    __half* A    = smem;                      // [64][520]
    __half* Wb   = smem + 33280;              // 2 x 16384
    float*  bias = (float*)(smem + 66048);    // 1664 floats

    const int tid  = threadIdx.x;
    const int lane = tid & 31, wid = tid >> 5;
    const int ql = lane & 3, gl = lane >> 2;

    // ---- biases into smem ----
    for (int i = tid; i < 512; i += 256) {
        bias[i] = b1[i]; bias[512 + i] = b2[i]; bias[1024 + i] = b3[i];
    }
    for (int i = tid; i < 128; i += 256) bias[1536 + i] = (i < 100) ? b4[i] : 0.0f;

    // ---- feature build: 4 threads per row, 32 feature cols each (0..127) ----
    {
        int row = tid >> 2, part = tid & 3;
        size_t gr = (size_t)blockIdx.x * 64 + row;
        float4 xv = *(const float4*)(x + gr * 4);
        float xa[4] = {xv.x, xv.y, xv.z, xv.w};
        float qn[4]; float diag2 = 0.0f; int idx = 0;
        #pragma unroll
        for (int d = 0; d < 4; d++) {
            float a = mnv[d], b = mxv[d];
            float bw = (b - a) * 0.0625f;
            diag2 += bw * bw;
            float s = (xa[d] - a) / (b - a) * 16.0f;
            int bi = (int)floorf(s);
            bi = min(max(bi, 0), 15);
            idx = idx * 16 + bi;
            qn[d] = (xa[d] - qm[d]) / qs[d];
        }
        float4 pv = *(const float4*)(pivots + (size_t)idx * 4);
        float dd = (xa[0]-pv.x)*(xa[0]-pv.x) + (xa[1]-pv.y)*(xa[1]-pv.y)
                 + (xa[2]-pv.z)*(xa[2]-pv.z) + (xa[3]-pv.w)*(xa[3]-pv.w);
        float dist = sqrtf(dd) * rsqrtf(diag2);
        const float* kr = knnd + (size_t)idx * 100;
        __half* Ar = A + row * 520;
        for (int c = part * 32; c < part * 32 + 32; c++) {
            float v;
            if (c < 4)        v = qn[c];
            else if (c == 4)  v = dist;
            else if (c < 105) v = (kr[c - 5] - km[c - 5]) / ks[c - 5];
            else              v = 0.0f;
            Ar[c] = __float2half_rn(v);
        }
    }
    __syncthreads();

    auto prefetch = [&](int p) {
        int nb = (p < NBIG) ? PIECE_BIG * 2 : PIECE_SML * 2;  // bytes
        const char* s = (const char*)(g_wp + piece_off(p));
        char* d = (char*)(Wb + (p & 1) * 16384);
        for (int i = tid * 16; i < nb; i += 256 * 16) cp16(d + i, s + i);
        asm volatile("cp.async.commit_group;" ::: "memory");
    };
    prefetch(0);

    const int NK[4] = {7, 32, 32, 32};
    const float inv = 1.0f / 1024.0f;
    float acc[4][8][4];
    int piece = 0;

    for (int L = 0; L < 4; L++) {
        #pragma unroll
        for (int m = 0; m < 4; m++)
            #pragma unroll
            for (int n = 0; n < 8; n++)
                #pragma unroll
                for (int i = 0; i < 4; i++) acc[m][n][i] = 0.0f;

        const bool active = (L < 3) || (wid < 2);
        const int  loOff  = (L < 3) ? 512 * 16 : 128 * 16;

        for (int kp = 0; kp < NK[L]; kp++, piece++) {
            asm volatile("cp.async.wait_group 0;" ::: "memory");
            __syncthreads();                     // buffer ready + prior reads done
            if (piece + 1 < NPIECE) prefetch(piece + 1);

            const __half* W = Wb + (piece & 1) * 16384;
            const int kb = kp * 16;

            uint32_t afr[4][4];
            #pragma unroll
            for (int m = 0; m < 4; m++) {
                const __half* Ab = A + (m * 16 + gl) * 520 + kb + 2 * ql;
                afr[m][0] = *(const uint32_t*)(Ab);
                afr[m][1] = *(const uint32_t*)(Ab + 8 * 520);
                afr[m][2] = *(const uint32_t*)(Ab + 8);
                afr[m][3] = *(const uint32_t*)(Ab + 8 * 520 + 8);
            }
            if (active) {
                #pragma unroll
                for (int pass = 0; pass < 2; pass++) {
                    const __half* Wp = W + pass * loOff;
                    #pragma unroll
                    for (int nt = 0; nt < 8; nt++) {
                        int n  = wid * 64 + nt * 8 + gl;
                        int sw = ((n >> 2) & 1) << 2;
                        const __half* Wr = Wp + n * 16;
                        uint32_t bb0 = *(const uint32_t*)(Wr + ((ql ^ sw) << 1));
                        uint32_t bb1 = *(const uint32_t*)(Wr + (((ql + 4) ^ sw) << 1));
                        #pragma unroll
                        for (int m = 0; m < 4; m++) {
                            asm volatile(
                                "mma.sync.aligned.m16n8k16.row.col.f32.f16.f16.f32 "
                                "{%0,%1,%2,%3}, {%4,%5,%6,%7}, {%8,%9}, {%0,%1,%2,%3};"
                                : "+f"(acc[m][nt][0]), "+f"(acc[m][nt][1]),
                                  "+f"(acc[m][nt][2]), "+f"(acc[m][nt][3])
                                : "r"(afr[m][0]), "r"(afr[m][1]),
                                  "r"(afr[m][2]), "r"(afr[m][3]),
                                  "r"(bb0), "r"(bb1));
                        }
                    }
                }
            }
        }
        __syncthreads();                         // all warps done reading A

        if (L < 3) {
            #pragma unroll
            for (int m = 0; m < 4; m++)
                #pragma unroll
                for (int nt = 0; nt < 8; nt++) {
                    int col = wid * 64 + nt * 8 + 2 * ql;
                    int r0  = m * 16 + gl;
                    float ba = bias[L * 512 + col], bbf = bias[L * 512 + col + 1];
                    float v00 = fmaxf(acc[m][nt][0] * inv + ba,  0.0f);
                    float v01 = fmaxf(acc[m][nt][1] * inv + bbf, 0.0f);
                    float v10 = fmaxf(acc[m][nt][2] * inv + ba,  0.0f);
                    float v11 = fmaxf(acc[m][nt][3] * inv + bbf, 0.0f);
                    *(__half2*)(A + r0 * 520 + col)       = __floats2half2_rn(v00, v01);
                    *(__half2*)(A + (r0 + 8) * 520 + col) = __floats2half2_rn(v10, v11);
                }
            __syncthreads();                     // next layer reads A
        } else if (wid < 2) {
            size_t rb = (size_t)blockIdx.x * 64;
            #pragma unroll
            for (int m = 0; m < 4; m++)
                #pragma unroll
                for (int nt = 0; nt < 8; nt++) {
                    int col = wid * 64 + nt * 8 + 2 * ql;
                    if (col >= 100) continue;
                    int r0 = m * 16 + gl;
                    float ba = bias[1536 + col], bbf = bias[1536 + col + 1];
                    float2 o0 = make_float2(acc[m][nt][0] * inv + ba,
                                            acc[m][nt][1] * inv + bbf);
                    float2 o1 = make_float2(acc[m][nt][2] * inv + ba,
                                            acc[m][nt][3] * inv + bbf);
                    *(float2*)(out + (rb + r0)     * 100 + col) = o0;
                    *(float2*)(out + (rb + r0 + 8) * 100 + col) = o1;
                }
        }
    }
}

// ---------------- launch ----------------------------------------------------
extern "C" void kernel_launch(void* const* d_in, const int* in_sizes, int n_in,
                              void* d_out, int out_size)
{
    const float* x   = (const float*)d_in[0];
    const float* mnv = (const float*)d_in[1];
    const float* mxv = (const float*)d_in[2];
    const float* pv  = (const float*)d_in[3];
    const float* kd  = (const float*)d_in[4];
    const float* qm  = (const float*)d_in[5];
    const float* qs  = (const float*)d_in[6];
    const float* km  = (const float*)d_in[7];
    const float* ks  = (const float*)d_in[8];
    const float* W1  = (const float*)d_in[9];
    const float* b1  = (const float*)d_in[10];
    const float* W2  = (const float*)d_in[11];
    const float* b2  = (const float*)d_in[12];
    const float* W3  = (const float*)d_in[13];
    const float* b3  = (const float*)d_in[14];
    const float* W4  = (const float*)d_in[15];
    const float* b4  = (const float*)d_in[16];

    cudaFuncSetAttribute(pivnet_main,
                         cudaFuncAttributeMaxDynamicSharedMemorySize, SMEM_BYTES);

    prep_weights<<<(NPIECE * 8192 + 255) / 256, 256>>>(W1, W2, W3, W4);
    pivnet_main<<<8192, 256, SMEM_BYTES>>>(x, mnv, mxv, pv, kd, qm, qs, km, ks,
                                           b1, b2, b3, b4, (float*)d_out);
}

// round 12
// speedup vs baseline: 1.1023x; 1.1023x over previous
#include <cuda_runtime.h>
#include <cuda_fp16.h>
#include <cstdint>

// ---------------------------------------------------------------------------
// PivNet fused MLP, GB300 sm_103a.  (R11: ldmatrix A-frags, fragment-packed
// B pieces loaded as LDS.128, layer-4 spread over all 8 warps.)
// B=524288, DIM=4, GRID=16, K=100, H=512, FEAT=105 (padded to 128 in layer 1).
// Per CTA: 64 rows. Activations fp16 in smem; full-layer fp32 accumulators in
// registers; weights pre-split fp16 hi+lo (x1024) streamed via cp.async.
// GEMM core: mma.sync.aligned.m16n8k16.row.col.f32.f16.f16.f32
// ---------------------------------------------------------------------------

#define NPIECE     103          // 7 (L1) + 32 (L2) + 32 (L3) + 32 (L4)
#define NBIG       71           // pieces with N=512 (L1..L3)
#define PIECE_BIG  16384        // halves: 16k x 512n x 2 (hi+lo)
#define PIECE_SML  4096         // halves: 16k x 128n x 2 (L4)

// smem layout (in halves):
//   A     [64][520]          @ 0       (66560 B)
//   Wbuf  2 x 16384          @ 33280   (65536 B)
//   bias  1664 floats        @ 66048   ( 6656 B)
#define SMEM_BYTES 139264

__device__ __align__(16) __half g_wp[NBIG * PIECE_BIG + 32 * PIECE_SML];

__host__ __device__ __forceinline__ int piece_off(int p) {
    return p < NBIG ? p * PIECE_BIG : NBIG * PIECE_BIG + (p - NBIG) * PIECE_SML;
}

// ---------------- weight prep: fp32 -> fragment-packed fp16 hi/lo ----------
// Per piece: [hi block][lo block], each block = [ntp][lane 32][4 b32 words].
// Word w of lane l in nt-pair ntp covers B col n = (ntp*2+(w>>1))*8 + (l>>2),
// k halves { 2*(l&3) + (w&1)*8, +1 }.  One LDS.128 per lane = frags for 2 nt.
__global__ void prep_weights(const float* __restrict__ W1, const float* __restrict__ W2,
                             const float* __restrict__ W3, const float* __restrict__ W4)
{
    int t = blockIdx.x * blockDim.x + threadIdx.x;
    const int TOT = NBIG * PIECE_BIG + 32 * PIECE_SML;
    if (t >= TOT) return;
    int p, q;
    if (t < NBIG * PIECE_BIG) { p = t / PIECE_BIG; q = t % PIECE_BIG; }
    else { int u = t - NBIG * PIECE_BIG; p = NBIG + u / PIECE_SML; q = u % PIECE_SML; }

    const float* W; int Kd, Nd, ld, k16;
    if (p < 7)       { W = W1; Kd = 105; Nd = 512; ld = 512; k16 = p;      }
    else if (p < 39) { W = W2; Kd = 512; Nd = 512; ld = 512; k16 = p - 7;  }
    else if (p < 71) { W = W3; Kd = 512; Nd = 512; ld = 512; k16 = p - 39; }
    else             { W = W4; Kd = 512; Nd = 100; ld = 100; k16 = p - 71; }

    int blkHalves = (p < NBIG) ? 8192 : 2048;
    int blk = q / blkHalves;             // 0 = hi, 1 = lo
    int i   = q % blkHalves;
    int h    = i & 1;
    int w    = (i >> 1) & 3;
    int lane = (i >> 3) & 31;
    int ntp  = i >> 8;
    int n  = (ntp * 2 + (w >> 1)) * 8 + (lane >> 2);
    int kk = 2 * (lane & 3) + (w & 1) * 8 + h;
    int gk = k16 * 16 + kk;

    float wv = 0.0f;
    if (gk < Kd && n < Nd) wv = W[(size_t)gk * ld + n] * 1024.0f;
    __half hi = __float2half_rn(wv);
    __half lo = __float2half_rn(wv - __half2float(hi));
    g_wp[piece_off(p) + blk * blkHalves + i] = blk ? lo : hi;
}

__device__ __forceinline__ void cp16(void* dst, const void* src) {
    uint32_t d = (uint32_t)__cvta_generic_to_shared(dst);
    asm volatile("cp.async.cg.shared.global [%0], [%1], 16;" :: "r"(d), "l"(src) : "memory");
}

__device__ __forceinline__ void ldsm4(uint32_t* a, uint32_t addr) {
    asm volatile("ldmatrix.sync.aligned.m8n8.x4.shared.b16 {%0,%1,%2,%3}, [%4];"
                 : "=r"(a[0]), "=r"(a[1]), "=r"(a[2]), "=r"(a[3]) : "r"(addr));
}

__device__ __forceinline__ void mma16816(float* c, const uint32_t* a,
                                         uint32_t b0, uint32_t b1) {
    asm volatile(
        "mma.sync.aligned.m16n8k16.row.col.f32.f16.f16.f32 "
        "{%0,%1,%2,%3}, {%4,%5,%6,%7}, {%8,%9}, {%0,%1,%2,%3};"
        : "+f"(c[0]), "+f"(c[1]), "+f"(c[2]), "+f"(c[3])
        : "r"(a[0]), "r"(a[1]), "r"(a[2]), "r"(a[3]), "r"(b0), "r"(b1));
}

// ---------------- main fused kernel ----------------------------------------
__global__ void __launch_bounds__(256, 1)
pivnet_main(const float* __restrict__ x,  const float* __restrict__ mnv,
            const float* __restrict__ mxv, const float* __restrict__ pivots,
            const float* __restrict__ knnd, const float* __restrict__ qm,
            const float* __restrict__ qs,  const float* __restrict__ km,
            const float* __restrict__ ks,  const float* __restrict__ b1,
            const float* __restrict__ b2,  const float* __restrict__ b3,
            const float* __restrict__ b4,  float* __restrict__ out)
{
    extern __shared__ __half smem[];
    __half* A    = smem;                      // [64][520]
    __half* Wb   = smem + 33280;              // 2 x 16384
    float*  bias = (float*)(smem + 66048);    // 1664 floats

    const int tid  = threadIdx.x;
    const int lane = tid & 31, wid = tid >> 5;
    const int ql = lane & 3, gl = lane >> 2;

    // ---- biases into smem ----
    for (int i = tid; i < 512; i += 256) {
        bias[i] = b1[i]; bias[512 + i] = b2[i]; bias[1024 + i] = b3[i];
    }
    for (int i = tid; i < 128; i += 256) bias[1536 + i] = (i < 100) ? b4[i] : 0.0f;

    // ---- feature build: 4 threads per row, 32 feature cols each (0..127) ----
    {
        int row = tid >> 2, part = tid & 3;
        size_t gr = (size_t)blockIdx.x * 64 + row;
        float4 xv = *(const float4*)(x + gr * 4);
        float xa[4] = {xv.x, xv.y, xv.z, xv.w};
        float qn[4]; float diag2 = 0.0f; int idx = 0;
        #pragma unroll
        for (int d = 0; d < 4; d++) {
            float a = mnv[d], b = mxv[d];
            float bw = (b - a) * 0.0625f;
            diag2 += bw * bw;
            float s = (xa[d] - a) / (b - a) * 16.0f;
            int bi = (int)floorf(s);
            bi = min(max(bi, 0), 15);
            idx = idx * 16 + bi;
            qn[d] = (xa[d] - qm[d]) / qs[d];
        }
        float4 pv = *(const float4*)(pivots + (size_t)idx * 4);
        float dd = (xa[0]-pv.x)*(xa[0]-pv.x) + (xa[1]-pv.y)*(xa[1]-pv.y)
                 + (xa[2]-pv.z)*(xa[2]-pv.z) + (xa[3]-pv.w)*(xa[3]-pv.w);
        float dist = sqrtf(dd) * rsqrtf(diag2);
        const float* kr = knnd + (size_t)idx * 100;
        __half* Ar = A + row * 520;
        for (int c = part * 32; c < part * 32 + 32; c++) {
            float v;
            if (c < 4)        v = qn[c];
            else if (c == 4)  v = dist;
            else if (c < 105) v = (kr[c - 5] - km[c - 5]) / ks[c - 5];
            else              v = 0.0f;
            Ar[c] = __float2half_rn(v);
        }
    }
    __syncthreads();

    auto prefetch = [&](int p) {
        int nb = (p < NBIG) ? PIECE_BIG * 2 : PIECE_SML * 2;  // bytes
        const char* s = (const char*)(g_wp + piece_off(p));
        char* d = (char*)(Wb + (p & 1) * 16384);
        for (int i = tid * 16; i < nb; i += 256 * 16) cp16(d + i, s + i);
        asm volatile("cp.async.commit_group;" ::: "memory");
    };
    prefetch(0);

    // ldmatrix per-thread row base (halves), add m*16*520 + kb per use
    const uint32_t As = (uint32_t)__cvta_generic_to_shared(A);
    const int rowa = (lane & 7) + ((lane >> 3) & 1) * 8;
    const int kadd = ((lane >> 4) & 1) * 8;
    const uint32_t abase = As + (uint32_t)(rowa * 520 + kadd) * 2;

    const int NK[4] = {7, 32, 32, 32};
    const float inv = 1.0f / 1024.0f;
    float acc[4][8][4];
    int piece = 0;

    for (int L = 0; L < 4; L++) {
        #pragma unroll
        for (int m = 0; m < 4; m++)
            #pragma unroll
            for (int n = 0; n < 8; n++)
                #pragma unroll
                for (int i = 0; i < 4; i++) acc[m][n][i] = 0.0f;

        const bool big = (L < 3);

        for (int kp = 0; kp < NK[L]; kp++, piece++) {
            asm volatile("cp.async.wait_group 0;" ::: "memory");
            __syncthreads();                     // buffer ready + prior reads done
            if (piece + 1 < NPIECE) prefetch(piece + 1);

            const __half* W = Wb + (piece & 1) * 16384;
            const int kb = kp * 16;

            uint32_t afr[4][4];
            #pragma unroll
            for (int m = 0; m < 4; m++)
                ldsm4(afr[m], abase + (uint32_t)(m * 16 * 520 + kb) * 2);

            if (big) {
                #pragma unroll
                for (int pass = 0; pass < 2; pass++) {
                    const __half* Wp = W + pass * 8192;
                    #pragma unroll
                    for (int j = 0; j < 4; j++) {
                        int ntp = wid * 4 + j;
                        uint4 bw = *(const uint4*)(Wp + (ntp * 32 + lane) * 8);
                        #pragma unroll
                        for (int m = 0; m < 4; m++)
                            mma16816(acc[m][2 * j],     afr[m], bw.x, bw.y);
                        #pragma unroll
                        for (int m = 0; m < 4; m++)
                            mma16816(acc[m][2 * j + 1], afr[m], bw.z, bw.w);
                    }
                }
            } else {
                #pragma unroll
                for (int pass = 0; pass < 2; pass++) {
                    const __half* Wp = W + pass * 2048;
                    uint4 bw = *(const uint4*)(Wp + (wid * 32 + lane) * 8);
                    #pragma unroll
                    for (int m = 0; m < 4; m++)
                        mma16816(acc[m][0], afr[m], bw.x, bw.y);
                    #pragma unroll
                    for (int m = 0; m < 4; m++)
                        mma16816(acc[m][1], afr[m], bw.z, bw.w);
                }
            }
        }
        __syncthreads();                         // all warps done reading A

        if (big) {
            #pragma unroll
            for (int m = 0; m < 4; m++)
                #pragma unroll
                for (int nt = 0; nt < 8; nt++) {
                    int col = wid * 64 + nt * 8 + 2 * ql;
                    int r0  = m * 16 + gl;
                    float ba = bias[L * 512 + col], bbf = bias[L * 512 + col + 1];
                    float v00 = fmaxf(acc[m][nt][0] * inv + ba,  0.0f);
                    float v01 = fmaxf(acc[m][nt][1] * inv + bbf, 0.0f);
                    float v10 = fmaxf(acc[m][nt][2] * inv + ba,  0.0f);
                    float v11 = fmaxf(acc[m][nt][3] * inv + bbf, 0.0f);
                    *(__half2*)(A + r0 * 520 + col)       = __floats2half2_rn(v00, v01);
                    *(__half2*)(A + (r0 + 8) * 520 + col) = __floats2half2_rn(v10, v11);
                }
            __syncthreads();                     // next layer reads A
        } else {
            // L4: warp w owns output cols [w*16, w*16+16)
            size_t rb = (size_t)blockIdx.x * 64;
            #pragma unroll
            for (int m = 0; m < 4; m++)
                #pragma unroll
                for (int e = 0; e < 2; e++) {
                    int col = wid * 16 + e * 8 + 2 * ql;
                    if (col >= 100) continue;
                    int r0 = m * 16 + gl;
                    float ba = bias[1536 + col], bbf = bias[1536 + col + 1];
                    float2 o0 = make_float2(acc[m][e][0] * inv + ba,
                                            acc[m][e][1] * inv + bbf);
                    float2 o1 = make_float2(acc[m][e][2] * inv + ba,
                                            acc[m][e][3] * inv + bbf);
                    *(float2*)(out + (rb + r0)     * 100 + col) = o0;
                    *(float2*)(out + (rb + r0 + 8) * 100 + col) = o1;
                }
        }
    }
}

// ---------------- launch ----------------------------------------------------
extern "C" void kernel_launch(void* const* d_in, const int* in_sizes, int n_in,
                              void* d_out, int out_size)
{
    const float* x   = (const float*)d_in[0];
    const float* mnv = (const float*)d_in[1];
    const float* mxv = (const float*)d_in[2];
    const float* pv  = (const float*)d_in[3];
    const float* kd  = (const float*)d_in[4];
    const float* qm  = (const float*)d_in[5];
    const float* qs  = (const float*)d_in[6];
    const float* km  = (const float*)d_in[7];
    const float* ks  = (const float*)d_in[8];
    const float* W1  = (const float*)d_in[9];
    const float* b1  = (const float*)d_in[10];
    const float* W2  = (const float*)d_in[11];
    const float* b2  = (const float*)d_in[12];
    const float* W3  = (const float*)d_in[13];
    const float* b3  = (const float*)d_in[14];
    const float* W4  = (const float*)d_in[15];
    const float* b4  = (const float*)d_in[16];

    cudaFuncSetAttribute(pivnet_main,
                         cudaFuncAttributeMaxDynamicSharedMemorySize, SMEM_BYTES);

    const int TOT = NBIG * PIECE_BIG + 32 * PIECE_SML;
    prep_weights<<<(TOT + 255) / 256, 256>>>(W1, W2, W3, W4);
    pivnet_main<<<8192, 256, SMEM_BYTES>>>(x, mnv, mxv, pv, kd, qm, qs, km, ks,
                                           b1, b2, b3, b4, (float*)d_out);
}

// round 14
// speedup vs baseline: 1.6934x; 1.5363x over previous
#include <cuda_runtime.h>
#include <cuda_fp16.h>
#include <cstdint>

// ---------------------------------------------------------------------------
// PivNet fused MLP, GB300 sm_103a (legacy mma.sync path; tcgen05 is not
// available under the harness's compute_103 PTX target).
// R13: 512 threads / 16 warps (4/SMSP), single-fp16 weights (no hi/lo),
// bias folded into accumulator init, 4-slot / depth-3 cp.async ring.
// B=524288, DIM=4, GRID=16, K=100, H=512, FEAT=105 (padded to 128).
// Per CTA: 64 rows. Warp w owns cols [32w, 32w+32) (L1-3) / [8w, 8w+8) (L4).
// GEMM core: mma.sync.aligned.m16n8k16.row.col.f32.f16.f16.f32
// ---------------------------------------------------------------------------

#define NP        103           // 7 (L1) + 32 (L2) + 32 (L3) + 32 (L4)
#define NBIG      71            // pieces with N=512 (L1..L3), 16KB each
#define BIG_H     8192          // halves per big piece
#define SML_H     2048          // halves per small piece (L4, N=128)

// smem bytes:
//   A    [64][520] halves @ 0        (66560)
//   Wbuf 4 x 16384        @ 66560    (65536)
//   bias 1664 floats      @ 132096   ( 6656)
#define WOFF_H     33280        // Wbuf offset in halves
#define BIAS_OFF_H 66048        // bias offset in halves
#define SMEM_BYTES 138752

__device__ __align__(16) __half g_wp[NBIG * BIG_H + 32 * SML_H];

__host__ __device__ __forceinline__ int phalf(int p) {
    return p < NBIG ? p * BIG_H : NBIG * BIG_H + (p - NBIG) * SML_H;
}

// ---------------- weight prep: fp32 -> fragment-packed fp16 ----------------
// Piece = [ntp][lane 32][4 b32 words]. Word w of lane l in nt-pair ntp is
// B col n = (ntp*2+(w>>1))*8 + (l>>2), k halves { 2*(l&3) + (w&1)*8, +1 }.
// One LDS.128 per lane = B fragments for 2 n8 tiles. (Layout validated R11.)
__global__ void prep_weights(const float* __restrict__ W1, const float* __restrict__ W2,
                             const float* __restrict__ W3, const float* __restrict__ W4)
{
    int t = blockIdx.x * blockDim.x + threadIdx.x;
    const int TOT = NBIG * BIG_H + 32 * SML_H;
    if (t >= TOT) return;
    int p, i;
    if (t < NBIG * BIG_H) { p = t >> 13; i = t & (BIG_H - 1); }
    else { int u = t - NBIG * BIG_H; p = NBIG + (u >> 11); i = u & (SML_H - 1); }

    const float* W; int Kd, Nd, ld, k16;
    if (p < 7)       { W = W1; Kd = 105; Nd = 512; ld = 512; k16 = p;      }
    else if (p < 39) { W = W2; Kd = 512; Nd = 512; ld = 512; k16 = p - 7;  }
    else if (p < 71) { W = W3; Kd = 512; Nd = 512; ld = 512; k16 = p - 39; }
    else             { W = W4; Kd = 512; Nd = 100; ld = 100; k16 = p - 71; }

    int h    = i & 1;
    int w    = (i >> 1) & 3;
    int lane = (i >> 3) & 31;
    int ntp  = i >> 8;
    int n  = (ntp * 2 + (w >> 1)) * 8 + (lane >> 2);
    int kk = 2 * (lane & 3) + (w & 1) * 8 + h;
    int gk = k16 * 16 + kk;

    float wv = 0.0f;
    if (gk < Kd && n < Nd) wv = W[(size_t)gk * ld + n];
    g_wp[phalf(p) + i] = __float2half_rn(wv);
}

__device__ __forceinline__ void cp16s(uint32_t dst, const void* src) {
    asm volatile("cp.async.cg.shared.global [%0], [%1], 16;" :: "r"(dst), "l"(src) : "memory");
}
__device__ __forceinline__ void ldsm4(uint32_t* a, uint32_t addr) {
    asm volatile("ldmatrix.sync.aligned.m8n8.x4.shared.b16 {%0,%1,%2,%3}, [%4];"
                 : "=r"(a[0]), "=r"(a[1]), "=r"(a[2]), "=r"(a[3]) : "r"(addr));
}
__device__ __forceinline__ void mma16816(float* c, const uint32_t* a,
                                         uint32_t b0, uint32_t b1) {
    asm volatile(
        "mma.sync.aligned.m16n8k16.row.col.f32.f16.f16.f32 "
        "{%0,%1,%2,%3}, {%4,%5,%6,%7}, {%8,%9}, {%0,%1,%2,%3};"
        : "+f"(c[0]), "+f"(c[1]), "+f"(c[2]), "+f"(c[3])
        : "r"(a[0]), "r"(a[1]), "r"(a[2]), "r"(a[3]), "r"(b0), "r"(b1));
}

// ---------------- main fused kernel ----------------------------------------
__global__ void __launch_bounds__(512, 1)
pivnet_main(const float* __restrict__ x,   const float* __restrict__ mnv,
            const float* __restrict__ mxv,  const float* __restrict__ pivots,
            const float* __restrict__ knnd, const float* __restrict__ qm,
            const float* __restrict__ qs,   const float* __restrict__ km,
            const float* __restrict__ ks,   const float* __restrict__ b1,
            const float* __restrict__ b2,   const float* __restrict__ b3,
            const float* __restrict__ b4,   float* __restrict__ out)
{
    extern __shared__ __half smem[];
    __half* A    = smem;                      // [64][520]
    __half* Wb   = smem + WOFF_H;             // 4 x 8192 halves
    float*  bias = (float*)(smem + BIAS_OFF_H);

    const int tid  = threadIdx.x;
    const int lane = tid & 31, wid = tid >> 5;   // 16 warps
    const int ql = lane & 3, gl = lane >> 2;

    // ---- start streaming the first 3 weight pieces (overlaps everything) ----
    const uint32_t Wbase = (uint32_t)__cvta_generic_to_shared(Wb);
    auto prefetch = [&](int p) {
        int nb = (p < NBIG) ? BIG_H * 2 : SML_H * 2;   // bytes
        const char* s = (const char*)(g_wp + phalf(p));
        uint32_t d = Wbase + (p & 3) * 16384;
        for (int off = tid * 16; off < nb; off += 512 * 16)
            cp16s(d + off, s + off);
    };
    prefetch(0); asm volatile("cp.async.commit_group;" ::: "memory");
    prefetch(1); asm volatile("cp.async.commit_group;" ::: "memory");
    prefetch(2); asm volatile("cp.async.commit_group;" ::: "memory");

    // ---- biases into smem ----
    for (int i = tid; i < 512; i += 512) {
        bias[i] = b1[i]; bias[512 + i] = b2[i]; bias[1024 + i] = b3[i];
    }
    if (tid < 128) bias[1536 + tid] = (tid < 100) ? b4[tid] : 0.0f;

    // ---- feature build: 8 threads per row, 16 cols each (pad to 128) ----
    {
        int row = tid >> 3, part = tid & 7;
        size_t gr = (size_t)blockIdx.x * 64 + row;
        float4 xv = *(const float4*)(x + gr * 4);
        float xa[4] = {xv.x, xv.y, xv.z, xv.w};
        float qn[4]; float diag2 = 0.0f; int idx = 0;
        #pragma unroll
        for (int d = 0; d < 4; d++) {
            float a = mnv[d], b = mxv[d];
            float bw = (b - a) * 0.0625f;
            diag2 += bw * bw;
            float s = (xa[d] - a) / (b - a) * 16.0f;
            int bi = (int)floorf(s);
            bi = min(max(bi, 0), 15);
            idx = idx * 16 + bi;
            qn[d] = (xa[d] - qm[d]) / qs[d];
        }
        float4 pv = *(const float4*)(pivots + (size_t)idx * 4);
        float dd = (xa[0]-pv.x)*(xa[0]-pv.x) + (xa[1]-pv.y)*(xa[1]-pv.y)
                 + (xa[2]-pv.z)*(xa[2]-pv.z) + (xa[3]-pv.w)*(xa[3]-pv.w);
        float dist = sqrtf(dd) * rsqrtf(diag2);
        const float* kr = knnd + (size_t)idx * 100;
        __half* Ar = A + row * 520;
        for (int c = part * 16; c < part * 16 + 16; c++) {
            float v;
            if (c < 4)        v = qn[c];
            else if (c == 4)  v = dist;
            else if (c < 105) v = (kr[c - 5] - km[c - 5]) / ks[c - 5];
            else              v = 0.0f;
            Ar[c] = __float2half_rn(v);
        }
    }
    // A is consumed after the first loop-top __syncthreads.

    // ldmatrix per-thread base (halves): rows of the m16 tile + k-half select
    const uint32_t As = (uint32_t)__cvta_generic_to_shared(A);
    const int rowa = (lane & 7) + ((lane >> 3) & 1) * 8;
    const int kadd = ((lane >> 4) & 1) * 8;
    const uint32_t abase = As + (uint32_t)(rowa * 520 + kadd) * 2;

    const int KPs[4] = {7, 32, 32, 32};
    float acc[4][4][4];
    int piece = 0;

    #pragma unroll
    for (int L = 0; L < 4; L++) {
        const int NTW = (L < 3) ? 4 : 1;              // n8 tiles per warp
        const int cb  = (L < 3) ? wid * 32 : wid * 8; // warp's first output col
        const int bof = L * 512;                      // bias base (L=3 -> 1536)

        // init accumulators with bias (folds epilogue add)
        #pragma unroll
        for (int m = 0; m < 4; m++)
            #pragma unroll
            for (int nt = 0; nt < NTW; nt++) {
                int c = bof + cb + nt * 8 + 2 * ql;
                float v0 = bias[c], v1 = bias[c + 1];
                acc[m][nt][0] = v0; acc[m][nt][1] = v1;
                acc[m][nt][2] = v0; acc[m][nt][3] = v1;
            }

        for (int kp = 0; kp < KPs[L]; kp++, piece++) {
            asm volatile("cp.async.wait_group 2;" ::: "memory");
            __syncthreads();                 // piece's slot visible; prev reads done
            if (piece + 3 < NP) prefetch(piece + 3);
            asm volatile("cp.async.commit_group;" ::: "memory");

            const __half* Wp = Wb + (piece & 3) * BIG_H;
            const int kb = kp * 16;

            uint32_t afr[4][4];
            #pragma unroll
            for (int m = 0; m < 4; m++)
                ldsm4(afr[m], abase + (uint32_t)(m * 16 * 520 + kb) * 2);

            if (L < 3) {
                #pragma unroll
                for (int j = 0; j < 2; j++) {
                    uint4 bw = *(const uint4*)(Wp + ((wid * 2 + j) * 32 + lane) * 8);
                    #pragma unroll
                    for (int m = 0; m < 4; m++)
                        mma16816(acc[m][2 * j],     afr[m], bw.x, bw.y);
                    #pragma unroll
                    for (int m = 0; m < 4; m++)
                        mma16816(acc[m][2 * j + 1], afr[m], bw.z, bw.w);
                }
            } else {
                uint2 bw = *(const uint2*)(Wp + ((wid >> 1) * 32 + lane) * 8 + (wid & 1) * 4);
                #pragma unroll
                for (int m = 0; m < 4; m++)
                    mma16816(acc[m][0], afr[m], bw.x, bw.y);
            }
        }
        __syncthreads();                     // all warps done reading A this layer

        if (L < 3) {
            #pragma unroll
            for (int m = 0; m < 4; m++)
                #pragma unroll
                for (int nt = 0; nt < 4; nt++) {
                    int col = cb + nt * 8 + 2 * ql;
                    int r0  = m * 16 + gl;
                    float v00 = fmaxf(acc[m][nt][0], 0.0f);
                    float v01 = fmaxf(acc[m][nt][1], 0.0f);
                    float v10 = fmaxf(acc[m][nt][2], 0.0f);
                    float v11 = fmaxf(acc[m][nt][3], 0.0f);
                    *(__half2*)(A + r0 * 520 + col)       = __floats2half2_rn(v00, v01);
                    *(__half2*)(A + (r0 + 8) * 520 + col) = __floats2half2_rn(v10, v11);
                }
            // next layer's loop-top __syncthreads publishes the new A
        } else {
            size_t rb = (size_t)blockIdx.x * 64;
            int col = cb + 2 * ql;           // cols 0..127, valid < 100
            if (col < 100) {
                #pragma unroll
                for (int m = 0; m < 4; m++) {
                    int r0 = m * 16 + gl;
                    *(float2*)(out + (rb + r0)     * 100 + col) =
                        make_float2(acc[m][0][0], acc[m][0][1]);
                    *(float2*)(out + (rb + r0 + 8) * 100 + col) =
                        make_float2(acc[m][0][2], acc[m][0][3]);
                }
            }
        }
    }
}

// ---------------- launch ----------------------------------------------------
extern "C" void kernel_launch(void* const* d_in, const int* in_sizes, int n_in,
                              void* d_out, int out_size)
{
    const float* x   = (const float*)d_in[0];
    const float* mnv = (const float*)d_in[1];
    const float* mxv = (const float*)d_in[2];
    const float* pv  = (const float*)d_in[3];
    const float* kd  = (const float*)d_in[4];
    const float* qm  = (const float*)d_in[5];
    const float* qs  = (const float*)d_in[6];
    const float* km  = (const float*)d_in[7];
    const float* ks  = (const float*)d_in[8];
    const float* W1  = (const float*)d_in[9];
    const float* b1  = (const float*)d_in[10];
    const float* W2  = (const float*)d_in[11];
    const float* b2  = (const float*)d_in[12];
    const float* W3  = (const float*)d_in[13];
    const float* b3  = (const float*)d_in[14];
    const float* W4  = (const float*)d_in[15];
    const float* b4  = (const float*)d_in[16];

    cudaFuncSetAttribute(pivnet_main,
                         cudaFuncAttributeMaxDynamicSharedMemorySize, SMEM_BYTES);

    const int TOT = NBIG * BIG_H + 32 * SML_H;
    prep_weights<<<(TOT + 255) / 256, 256>>>(W1, W2, W3, W4);
    pivnet_main<<<8192, 512, SMEM_BYTES>>>(x, mnv, mxv, pv, kd, qm, qs, km, ks,
                                           b1, b2, b3, b4, (float*)d_out);
}

// round 15
// speedup vs baseline: 1.8015x; 1.0638x over previous
#include <cuda_runtime.h>
#include <cuda_fp16.h>
#include <cstdint>

// ---------------------------------------------------------------------------
// PivNet fused MLP, GB300 sm_103a (legacy mma.sync path; tcgen05 unavailable
// under the harness's compute_103 PTX target).
// R14: software-pipelined fragments (ping-pong A/B register buffers) so the
// post-barrier LDSM/LDS latency hides under the previous piece's 16 HMMA.
// 512 threads / 16 warps (4/SMSP), single-fp16 weights, bias folded into
// accumulator init, 4-slot / depth-3 cp.async ring.
// B=524288, DIM=4, GRID=16, K=100, H=512, FEAT=105 (padded to 128).
// Per CTA: 64 rows. Warp w owns cols [32w,32w+32) (L1-3) / [8w,8w+8) (L4).
// ---------------------------------------------------------------------------

#define NP        103           // 7 (L1) + 32 (L2) + 32 (L3) + 32 (L4)
#define NBIG      71            // pieces with N=512 (L1..L3), 16KB each
#define BIG_H     8192          // halves per big piece
#define SML_H     2048          // halves per small piece (L4, N=128)

// smem bytes:
//   A    [64][520] halves @ 0        (66560)
//   Wbuf 4 x 16384        @ 66560    (65536)
//   bias 1664 floats      @ 132096   ( 6656)
#define WOFF_H     33280        // Wbuf offset in halves
#define BIAS_OFF_H 66048        // bias offset in halves
#define SMEM_BYTES 138752

__device__ __align__(16) __half g_wp[NBIG * BIG_H + 32 * SML_H];

__host__ __device__ __forceinline__ int phalf(int p) {
    return p < NBIG ? p * BIG_H : NBIG * BIG_H + (p - NBIG) * SML_H;
}

// ---------------- weight prep: fp32 -> fragment-packed fp16 ----------------
// Piece = [ntp][lane 32][4 b32 words]. Word w of lane l in nt-pair ntp is
// B col n = (ntp*2+(w>>1))*8 + (l>>2), k halves { 2*(l&3) + (w&1)*8, +1 }.
// One LDS.128 per lane = B fragments for 2 n8 tiles. (Layout validated R11.)
__global__ void prep_weights(const float* __restrict__ W1, const float* __restrict__ W2,
                             const float* __restrict__ W3, const float* __restrict__ W4)
{
    int t = blockIdx.x * blockDim.x + threadIdx.x;
    const int TOT = NBIG * BIG_H + 32 * SML_H;
    if (t >= TOT) return;
    int p, i;
    if (t < NBIG * BIG_H) { p = t >> 13; i = t & (BIG_H - 1); }
    else { int u = t - NBIG * BIG_H; p = NBIG + (u >> 11); i = u & (SML_H - 1); }

    const float* W; int Kd, Nd, ld, k16;
    if (p < 7)       { W = W1; Kd = 105; Nd = 512; ld = 512; k16 = p;      }
    else if (p < 39) { W = W2; Kd = 512; Nd = 512; ld = 512; k16 = p - 7;  }
    else if (p < 71) { W = W3; Kd = 512; Nd = 512; ld = 512; k16 = p - 39; }
    else             { W = W4; Kd = 512; Nd = 100; ld = 100; k16 = p - 71; }

    int h    = i & 1;
    int w    = (i >> 1) & 3;
    int lane = (i >> 3) & 31;
    int ntp  = i >> 8;
    int n  = (ntp * 2 + (w >> 1)) * 8 + (lane >> 2);
    int kk = 2 * (lane & 3) + (w & 1) * 8 + h;
    int gk = k16 * 16 + kk;

    float wv = 0.0f;
    if (gk < Kd && n < Nd) wv = W[(size_t)gk * ld + n];
    g_wp[phalf(p) + i] = __float2half_rn(wv);
}

__device__ __forceinline__ void cp16s(uint32_t dst, const void* src) {
    asm volatile("cp.async.cg.shared.global [%0], [%1], 16;" :: "r"(dst), "l"(src) : "memory");
}
__device__ __forceinline__ void ldsm4(uint32_t* a, uint32_t addr) {
    asm volatile("ldmatrix.sync.aligned.m8n8.x4.shared.b16 {%0,%1,%2,%3}, [%4];"
                 : "=r"(a[0]), "=r"(a[1]), "=r"(a[2]), "=r"(a[3]) : "r"(addr));
}
__device__ __forceinline__ void mma16816(float* c, const uint32_t* a,
                                         uint32_t b0, uint32_t b1) {
    asm volatile(
        "mma.sync.aligned.m16n8k16.row.col.f32.f16.f16.f32 "
        "{%0,%1,%2,%3}, {%4,%5,%6,%7}, {%8,%9}, {%0,%1,%2,%3};"
        : "+f"(c[0]), "+f"(c[1]), "+f"(c[2]), "+f"(c[3])
        : "r"(a[0]), "r"(a[1]), "r"(a[2]), "r"(a[3]), "r"(b0), "r"(b1));
}

// fragment load macros (pbase/abase/Wb/wid/lane captured from enclosing scope)
#define LOAD_BIG(AF, BF, kpv) do {                                            \
    const int kb_ = (kpv) * 16;                                               \
    ldsm4(AF[0], abase + (uint32_t)(kb_) * 2);                                \
    ldsm4(AF[1], abase + (uint32_t)(16 * 520 + kb_) * 2);                     \
    ldsm4(AF[2], abase + (uint32_t)(32 * 520 + kb_) * 2);                     \
    ldsm4(AF[3], abase + (uint32_t)(48 * 520 + kb_) * 2);                     \
    const __half* Wp_ = Wb + ((pbase + (kpv)) & 3) * BIG_H;                   \
    BF[0] = *(const uint4*)(Wp_ + ((wid * 2 + 0) * 32 + lane) * 8);           \
    BF[1] = *(const uint4*)(Wp_ + ((wid * 2 + 1) * 32 + lane) * 8);           \
} while (0)

#define MMA_BIG(AF, BF) do {                                                  \
    _Pragma("unroll")                                                         \
    for (int m_ = 0; m_ < 4; m_++) mma16816(acc[m_][0], AF[m_], BF[0].x, BF[0].y); \
    _Pragma("unroll")                                                         \
    for (int m_ = 0; m_ < 4; m_++) mma16816(acc[m_][1], AF[m_], BF[0].z, BF[0].w); \
    _Pragma("unroll")                                                         \
    for (int m_ = 0; m_ < 4; m_++) mma16816(acc[m_][2], AF[m_], BF[1].x, BF[1].y); \
    _Pragma("unroll")                                                         \
    for (int m_ = 0; m_ < 4; m_++) mma16816(acc[m_][3], AF[m_], BF[1].z, BF[1].w); \
} while (0)

#define LOAD_SML(AF, BF, kpv) do {                                            \
    const int kb_ = (kpv) * 16;                                               \
    ldsm4(AF[0], abase + (uint32_t)(kb_) * 2);                                \
    ldsm4(AF[1], abase + (uint32_t)(16 * 520 + kb_) * 2);                     \
    ldsm4(AF[2], abase + (uint32_t)(32 * 520 + kb_) * 2);                     \
    ldsm4(AF[3], abase + (uint32_t)(48 * 520 + kb_) * 2);                     \
    const __half* Wp_ = Wb + ((pbase + (kpv)) & 3) * BIG_H;                   \
    BF = *(const uint2*)(Wp_ + ((wid >> 1) * 32 + lane) * 8 + (wid & 1) * 4); \
} while (0)

#define MMA_SML(AF, BF) do {                                                  \
    _Pragma("unroll")                                                         \
    for (int m_ = 0; m_ < 4; m_++) mma16816(acc[m_][0], AF[m_], BF.x, BF.y);  \
} while (0)

// ---------------- main fused kernel ----------------------------------------
__global__ void __launch_bounds__(512, 1)
pivnet_main(const float* __restrict__ x,   const float* __restrict__ mnv,
            const float* __restrict__ mxv,  const float* __restrict__ pivots,
            const float* __restrict__ knnd, const float* __restrict__ qm,
            const float* __restrict__ qs,   const float* __restrict__ km,
            const float* __restrict__ ks,   const float* __restrict__ b1,
            const float* __restrict__ b2,   const float* __restrict__ b3,
            const float* __restrict__ b4,   float* __restrict__ out)
{
    extern __shared__ __half smem[];
    __half* A    = smem;                      // [64][520]
    __half* Wb   = smem + WOFF_H;             // 4 x 8192 halves
    float*  bias = (float*)(smem + BIAS_OFF_H);

    const int tid  = threadIdx.x;
    const int lane = tid & 31, wid = tid >> 5;   // 16 warps
    const int ql = lane & 3, gl = lane >> 2;

    // ---- start streaming the first 3 weight pieces (overlaps everything) ----
    const uint32_t Wbase = (uint32_t)__cvta_generic_to_shared(Wb);
    auto prefetch = [&](int p) {
        int nb = (p < NBIG) ? BIG_H * 2 : SML_H * 2;   // bytes
        const char* s = (const char*)(g_wp + phalf(p));
        uint32_t d = Wbase + (p & 3) * 16384;
        for (int off = tid * 16; off < nb; off += 512 * 16)
            cp16s(d + off, s + off);
    };
    prefetch(0); asm volatile("cp.async.commit_group;" ::: "memory");
    prefetch(1); asm volatile("cp.async.commit_group;" ::: "memory");
    prefetch(2); asm volatile("cp.async.commit_group;" ::: "memory");

    // sync_for(q): slot of piece q is ready & visible; kick q+3 into ring
    auto sync_for = [&](int q) {
        asm volatile("cp.async.wait_group 2;" ::: "memory");
        __syncthreads();
        if (q + 3 < NP) prefetch(q + 3);
        asm volatile("cp.async.commit_group;" ::: "memory");
    };

    // ---- biases into smem ----
    {
        int i = tid;
        if (i < 512) { bias[i] = b1[i]; bias[512 + i] = b2[i]; bias[1024 + i] = b3[i]; }
        if (i < 128) bias[1536 + i] = (i < 100) ? b4[i] : 0.0f;
    }

    // ---- feature build: 8 threads per row, 16 cols each (pad to 128) ----
    {
        int row = tid >> 3, part = tid & 7;
        size_t gr = (size_t)blockIdx.x * 64 + row;
        float4 xv = *(const float4*)(x + gr * 4);
        float xa[4] = {xv.x, xv.y, xv.z, xv.w};
        float qn[4]; float diag2 = 0.0f; int idx = 0;
        #pragma unroll
        for (int d = 0; d < 4; d++) {
            float a = mnv[d], b = mxv[d];
            float bw = (b - a) * 0.0625f;
            diag2 += bw * bw;
            float s = (xa[d] - a) / (b - a) * 16.0f;
            int bi = (int)floorf(s);
            bi = min(max(bi, 0), 15);
            idx = idx * 16 + bi;
            qn[d] = (xa[d] - qm[d]) / qs[d];
        }
        float4 pv = *(const float4*)(pivots + (size_t)idx * 4);
        float dd = (xa[0]-pv.x)*(xa[0]-pv.x) + (xa[1]-pv.y)*(xa[1]-pv.y)
                 + (xa[2]-pv.z)*(xa[2]-pv.z) + (xa[3]-pv.w)*(xa[3]-pv.w);
        float dist = sqrtf(dd) * rsqrtf(diag2);
        const float* kr = knnd + (size_t)idx * 100;
        __half* Ar = A + row * 520;
        for (int c = part * 16; c < part * 16 + 16; c++) {
            float v;
            if (c < 4)        v = qn[c];
            else if (c == 4)  v = dist;
            else if (c < 105) v = (kr[c - 5] - km[c - 5]) / ks[c - 5];
            else              v = 0.0f;
            Ar[c] = __float2half_rn(v);
        }
    }
    // A is published by the first sync_for below.

    // ldmatrix per-thread base (halves): rows of the m16 tile + k-half select
    const uint32_t As = (uint32_t)__cvta_generic_to_shared(A);
    const int rowa = (lane & 7) + ((lane >> 3) & 1) * 8;
    const int kadd = ((lane >> 4) & 1) * 8;
    const uint32_t abase = As + (uint32_t)(rowa * 520 + kadd) * 2;

    float acc[4][4][4];
    int piece = 0;

    // ================= layers 1-3 (N=512) =================
    for (int L = 0; L < 3; L++) {
        const int KP = (L == 0) ? 7 : 32;
        const int cb = wid * 32;

        #pragma unroll
        for (int m = 0; m < 4; m++)
            #pragma unroll
            for (int nt = 0; nt < 4; nt++) {
                int c = L * 512 + cb + nt * 8 + 2 * ql;
                float v0 = bias[c], v1 = bias[c + 1];
                acc[m][nt][0] = v0; acc[m][nt][1] = v1;
                acc[m][nt][2] = v0; acc[m][nt][3] = v1;
            }

        const int pbase = piece;
        uint32_t af0[4][4], af1[4][4];
        uint4 bf0[2], bf1[2];

        sync_for(pbase);
        LOAD_BIG(af0, bf0, 0);
        int kp = 0;
        while (true) {
            if (kp + 1 < KP) { sync_for(pbase + kp + 1); LOAD_BIG(af1, bf1, kp + 1); }
            MMA_BIG(af0, bf0);
            if (++kp >= KP) break;
            if (kp + 1 < KP) { sync_for(pbase + kp + 1); LOAD_BIG(af0, bf0, kp + 1); }
            MMA_BIG(af1, bf1);
            if (++kp >= KP) break;
        }
        piece = pbase + KP;
        __syncthreads();                     // all warps done reading A this layer

        #pragma unroll
        for (int m = 0; m < 4; m++)
            #pragma unroll
            for (int nt = 0; nt < 4; nt++) {
                int col = cb + nt * 8 + 2 * ql;
                int r0  = m * 16 + gl;
                float v00 = fmaxf(acc[m][nt][0], 0.0f);
                float v01 = fmaxf(acc[m][nt][1], 0.0f);
                float v10 = fmaxf(acc[m][nt][2], 0.0f);
                float v11 = fmaxf(acc[m][nt][3], 0.0f);
                *(__half2*)(A + r0 * 520 + col)       = __floats2half2_rn(v00, v01);
                *(__half2*)(A + (r0 + 8) * 520 + col) = __floats2half2_rn(v10, v11);
            }
        // next layer's first sync_for publishes the new A
    }

    // ================= layer 4 (N=100 -> 128) =================
    {
        const int KP = 32;
        const int cb = wid * 8;

        #pragma unroll
        for (int m = 0; m < 4; m++) {
            int c = 1536 + cb + 2 * ql;
            float v0 = bias[c], v1 = bias[c + 1];
            acc[m][0][0] = v0; acc[m][0][1] = v1;
            acc[m][0][2] = v0; acc[m][0][3] = v1;
        }

        const int pbase = piece;
        uint32_t af0[4][4], af1[4][4];
        uint2 bs0, bs1;

        sync_for(pbase);
        LOAD_SML(af0, bs0, 0);
        int kp = 0;
        while (true) {
            if (kp + 1 < KP) { sync_for(pbase + kp + 1); LOAD_SML(af1, bs1, kp + 1); }
            MMA_SML(af0, bs0);
            if (++kp >= KP) break;
            if (kp + 1 < KP) { sync_for(pbase + kp + 1); LOAD_SML(af0, bs0, kp + 1); }
            MMA_SML(af1, bs1);
            if (++kp >= KP) break;
        }

        size_t rb = (size_t)blockIdx.x * 64;
        int col = cb + 2 * ql;               // cols 0..127, valid < 100
        if (col < 100) {
            #pragma unroll
            for (int m = 0; m < 4; m++) {
                int r0 = m * 16 + gl;
                *(float2*)(out + (rb + r0)     * 100 + col) =
                    make_float2(acc[m][0][0], acc[m][0][1]);
                *(float2*)(out + (rb + r0 + 8) * 100 + col) =
                    make_float2(acc[m][0][2], acc[m][0][3]);
            }
        }
    }
}

// ---------------- launch ----------------------------------------------------
extern "C" void kernel_launch(void* const* d_in, const int* in_sizes, int n_in,
                              void* d_out, int out_size)
{
    const float* x   = (const float*)d_in[0];
    const float* mnv = (const float*)d_in[1];
    const float* mxv = (const float*)d_in[2];
    const float* pv  = (const float*)d_in[3];
    const float* kd  = (const float*)d_in[4];
    const float* qm  = (const float*)d_in[5];
    const float* qs  = (const float*)d_in[6];
    const float* km  = (const float*)d_in[7];
    const float* ks  = (const float*)d_in[8];
    const float* W1  = (const float*)d_in[9];
    const float* b1  = (const float*)d_in[10];
    const float* W2  = (const float*)d_in[11];
    const float* b2  = (const float*)d_in[12];
    const float* W3  = (const float*)d_in[13];
    const float* b3  = (const float*)d_in[14];
    const float* W4  = (const float*)d_in[15];
    const float* b4  = (const float*)d_in[16];

    cudaFuncSetAttribute(pivnet_main,
                         cudaFuncAttributeMaxDynamicSharedMemorySize, SMEM_BYTES);

    const int TOT = NBIG * BIG_H + 32 * SML_H;
    prep_weights<<<(TOT + 255) / 256, 256>>>(W1, W2, W3, W4);
    pivnet_main<<<8192, 512, SMEM_BYTES>>>(x, mnv, mxv, pv, kd, qm, qs, km, ks,
                                           b1, b2, b3, b4, (float*)d_out);
}

// round 16
// speedup vs baseline: 2.6198x; 1.4542x over previous
#include <cuda_runtime.h>
#include <cuda_fp16.h>
#include <cstdint>

// ---------------------------------------------------------------------------
// PivNet fused MLP, GB300 sm_103a (legacy mma.sync path; tcgen05 unavailable
// under the harness's compute_103 PTX target).
// R15: B fragments loaded global->register (coalesced LDG.128 from the
// L2-resident fragment-packed weight image) -- no smem weight ring, no
// cp.async, no per-piece barriers. A fragments via ldmatrix from smem.
// Ping-pong register pipelining of both A and B fragments.
// 512 threads / 16 warps (4/SMSP), single-fp16 weights, bias folded into
// accumulator init.
// B=524288, DIM=4, GRID=16, K=100, H=512, FEAT=105 (padded to 128).
// Per CTA: 64 rows. Warp w owns cols [32w,32w+32) (L1-3) / [8w,8w+8) (L4).
// ---------------------------------------------------------------------------

#define NBIG      71            // big pieces (N=512): 7 (L1) + 32 (L2) + 32 (L3)
#define BIG_H     8192          // halves per big piece
#define SML_H     2048          // halves per small piece (L4, N=128), 32 pieces

// smem bytes: A [64][520] halves (66560) + bias 1664 floats (6656)
#define BIAS_OFF_H 33280
#define SMEM_BYTES 73216

__device__ __align__(16) __half g_wp[NBIG * BIG_H + 32 * SML_H];

__host__ __device__ __forceinline__ int phalf(int p) {
    return p < NBIG ? p * BIG_H : NBIG * BIG_H + (p - NBIG) * SML_H;
}

// ---------------- weight prep: fp32 -> fragment-packed fp16 ----------------
// Piece = [ntp][lane 32][4 b32 words]. Word w of lane l in nt-pair ntp is
// B col n = (ntp*2+(w>>1))*8 + (l>>2), k halves { 2*(l&3) + (w&1)*8, +1 }.
// One 16B load per lane = B fragments for 2 n8 tiles. (Validated R11-R14.)
__global__ void prep_weights(const float* __restrict__ W1, const float* __restrict__ W2,
                             const float* __restrict__ W3, const float* __restrict__ W4)
{
    int t = blockIdx.x * blockDim.x + threadIdx.x;
    const int TOT = NBIG * BIG_H + 32 * SML_H;
    if (t >= TOT) return;
    int p, i;
    if (t < NBIG * BIG_H) { p = t >> 13; i = t & (BIG_H - 1); }
    else { int u = t - NBIG * BIG_H; p = NBIG + (u >> 11); i = u & (SML_H - 1); }

    const float* W; int Kd, Nd, ld, k16;
    if (p < 7)       { W = W1; Kd = 105; Nd = 512; ld = 512; k16 = p;      }
    else if (p < 39) { W = W2; Kd = 512; Nd = 512; ld = 512; k16 = p - 7;  }
    else if (p < 71) { W = W3; Kd = 512; Nd = 512; ld = 512; k16 = p - 39; }
    else             { W = W4; Kd = 512; Nd = 100; ld = 100; k16 = p - 71; }

    int h    = i & 1;
    int w    = (i >> 1) & 3;
    int lane = (i >> 3) & 31;
    int ntp  = i >> 8;
    int n  = (ntp * 2 + (w >> 1)) * 8 + (lane >> 2);
    int kk = 2 * (lane & 3) + (w & 1) * 8 + h;
    int gk = k16 * 16 + kk;

    float wv = 0.0f;
    if (gk < Kd && n < Nd) wv = W[(size_t)gk * ld + n];
    g_wp[phalf(p) + i] = __float2half_rn(wv);
}

__device__ __forceinline__ void ldsm4(uint32_t* a, uint32_t addr) {
    asm volatile("ldmatrix.sync.aligned.m8n8.x4.shared.b16 {%0,%1,%2,%3}, [%4];"
                 : "=r"(a[0]), "=r"(a[1]), "=r"(a[2]), "=r"(a[3]) : "r"(addr));
}
__device__ __forceinline__ void mma16816(float* c, const uint32_t* a,
                                         uint32_t b0, uint32_t b1) {
    asm volatile(
        "mma.sync.aligned.m16n8k16.row.col.f32.f16.f16.f32 "
        "{%0,%1,%2,%3}, {%4,%5,%6,%7}, {%8,%9}, {%0,%1,%2,%3};"
        : "+f"(c[0]), "+f"(c[1]), "+f"(c[2]), "+f"(c[3])
        : "r"(a[0]), "r"(a[1]), "r"(a[2]), "r"(a[3]), "r"(b0), "r"(b1));
}

// fragment loads (gW/gW4/abase/wid/lane captured from enclosing scope)
#define LOADB_BIG(BF, kpv) do {                                               \
    const __half* Wp_ = gW + (size_t)(kpv) * BIG_H;                           \
    BF[0] = *(const uint4*)(Wp_ + ((wid * 2 + 0) * 32 + lane) * 8);           \
    BF[1] = *(const uint4*)(Wp_ + ((wid * 2 + 1) * 32 + lane) * 8);           \
} while (0)

#define LOADB_SML(BF, kpv) do {                                               \
    const __half* Wp_ = gW4 + (size_t)(kpv) * SML_H;                          \
    BF = *(const uint2*)(Wp_ + ((wid >> 1) * 32 + lane) * 8 + (wid & 1) * 4); \
} while (0)

#define LOADA(AF, kpv) do {                                                   \
    const int kb_ = (kpv) * 16;                                               \
    ldsm4(AF[0], abase + (uint32_t)(kb_) * 2);                                \
    ldsm4(AF[1], abase + (uint32_t)(16 * 520 + kb_) * 2);                     \
    ldsm4(AF[2], abase + (uint32_t)(32 * 520 + kb_) * 2);                     \
    ldsm4(AF[3], abase + (uint32_t)(48 * 520 + kb_) * 2);                     \
} while (0)

#define MMA_BIG(AF, BF) do {                                                  \
    _Pragma("unroll")                                                         \
    for (int m_ = 0; m_ < 4; m_++) mma16816(acc[m_][0], AF[m_], BF[0].x, BF[0].y); \
    _Pragma("unroll")                                                         \
    for (int m_ = 0; m_ < 4; m_++) mma16816(acc[m_][1], AF[m_], BF[0].z, BF[0].w); \
    _Pragma("unroll")                                                         \
    for (int m_ = 0; m_ < 4; m_++) mma16816(acc[m_][2], AF[m_], BF[1].x, BF[1].y); \
    _Pragma("unroll")                                                         \
    for (int m_ = 0; m_ < 4; m_++) mma16816(acc[m_][3], AF[m_], BF[1].z, BF[1].w); \
} while (0)

#define MMA_SML(AF, BF) do {                                                  \
    _Pragma("unroll")                                                         \
    for (int m_ = 0; m_ < 4; m_++) mma16816(acc[m_][0], AF[m_], BF.x, BF.y);  \
} while (0)

// ---------------- main fused kernel ----------------------------------------
__global__ void __launch_bounds__(512, 1)
pivnet_main(const float* __restrict__ x,   const float* __restrict__ mnv,
            const float* __restrict__ mxv,  const float* __restrict__ pivots,
            const float* __restrict__ knnd, const float* __restrict__ qm,
            const float* __restrict__ qs,   const float* __restrict__ km,
            const float* __restrict__ ks,   const float* __restrict__ b1,
            const float* __restrict__ b2,   const float* __restrict__ b3,
            const float* __restrict__ b4,   float* __restrict__ out)
{
    extern __shared__ __half smem[];
    __half* A    = smem;                      // [64][520]
    float*  bias = (float*)(smem + BIAS_OFF_H);

    const int tid  = threadIdx.x;
    const int lane = tid & 31, wid = tid >> 5;   // 16 warps
    const int ql = lane & 3, gl = lane >> 2;

    // ---- biases into smem ----
    {
        int i = tid;
        if (i < 512) { bias[i] = b1[i]; bias[512 + i] = b2[i]; bias[1024 + i] = b3[i]; }
        if (i < 128) bias[1536 + i] = (i < 100) ? b4[i] : 0.0f;
    }

    // ---- feature build: 8 threads per row, 16 cols each (pad to 128) ----
    {
        int row = tid >> 3, part = tid & 7;
        size_t gr = (size_t)blockIdx.x * 64 + row;
        float4 xv = *(const float4*)(x + gr * 4);
        float xa[4] = {xv.x, xv.y, xv.z, xv.w};
        float qn[4]; float diag2 = 0.0f; int idx = 0;
        #pragma unroll
        for (int d = 0; d < 4; d++) {
            float a = mnv[d], b = mxv[d];
            float bw = (b - a) * 0.0625f;
            diag2 += bw * bw;
            float s = (xa[d] - a) / (b - a) * 16.0f;
            int bi = (int)floorf(s);
            bi = min(max(bi, 0), 15);
            idx = idx * 16 + bi;
            qn[d] = (xa[d] - qm[d]) / qs[d];
        }
        float4 pv = *(const float4*)(pivots + (size_t)idx * 4);
        float dd = (xa[0]-pv.x)*(xa[0]-pv.x) + (xa[1]-pv.y)*(xa[1]-pv.y)
                 + (xa[2]-pv.z)*(xa[2]-pv.z) + (xa[3]-pv.w)*(xa[3]-pv.w);
        float dist = sqrtf(dd) * rsqrtf(diag2);
        const float* kr = knnd + (size_t)idx * 100;
        __half* Ar = A + row * 520;
        for (int c = part * 16; c < part * 16 + 16; c++) {
            float v;
            if (c < 4)        v = qn[c];
            else if (c == 4)  v = dist;
            else if (c < 105) v = (kr[c - 5] - km[c - 5]) / ks[c - 5];
            else              v = 0.0f;
            Ar[c] = __float2half_rn(v);
        }
    }
    __syncthreads();                          // A + bias published

    // ldmatrix per-thread base (halves): rows of the m16 tile + k-half select
    const uint32_t As = (uint32_t)__cvta_generic_to_shared(A);
    const int rowa = (lane & 7) + ((lane >> 3) & 1) * 8;
    const int kadd = ((lane >> 4) & 1) * 8;
    const uint32_t abase = As + (uint32_t)(rowa * 520 + kadd) * 2;

    float acc[4][4][4];

    // ================= layers 1-3 (N=512) =================
    int pbase = 0;
    for (int L = 0; L < 3; L++) {
        const int KP = (L == 0) ? 7 : 32;
        const int cb = wid * 32;
        const __half* gW = g_wp + (size_t)pbase * BIG_H;

        #pragma unroll
        for (int m = 0; m < 4; m++)
            #pragma unroll
            for (int nt = 0; nt < 4; nt++) {
                int c = L * 512 + cb + nt * 8 + 2 * ql;
                float v0 = bias[c], v1 = bias[c + 1];
                acc[m][nt][0] = v0; acc[m][nt][1] = v1;
                acc[m][nt][2] = v0; acc[m][nt][3] = v1;
            }

        uint32_t af0[4][4], af1[4][4];
        uint4 bf0[2], bf1[2];

        LOADB_BIG(bf0, 0);
        LOADA(af0, 0);
        int kp = 0;
        while (true) {
            if (kp + 1 < KP) { LOADB_BIG(bf1, kp + 1); LOADA(af1, kp + 1); }
            MMA_BIG(af0, bf0);
            if (++kp >= KP) break;
            if (kp + 1 < KP) { LOADB_BIG(bf0, kp + 1); LOADA(af0, kp + 1); }
            MMA_BIG(af1, bf1);
            if (++kp >= KP) break;
        }
        pbase += KP;
        __syncthreads();                     // all warps done reading A this layer

        #pragma unroll
        for (int m = 0; m < 4; m++)
            #pragma unroll
            for (int nt = 0; nt < 4; nt++) {
                int col = cb + nt * 8 + 2 * ql;
                int r0  = m * 16 + gl;
                float v00 = fmaxf(acc[m][nt][0], 0.0f);
                float v01 = fmaxf(acc[m][nt][1], 0.0f);
                float v10 = fmaxf(acc[m][nt][2], 0.0f);
                float v11 = fmaxf(acc[m][nt][3], 0.0f);
                *(__half2*)(A + r0 * 520 + col)       = __floats2half2_rn(v00, v01);
                *(__half2*)(A + (r0 + 8) * 520 + col) = __floats2half2_rn(v10, v11);
            }
        __syncthreads();                     // new A published for next layer
    }

    // ================= layer 4 (N=100 -> 128) =================
    {
        const int KP = 32;
        const int cb = wid * 8;
        const __half* gW4 = g_wp + (size_t)NBIG * BIG_H;

        #pragma unroll
        for (int m = 0; m < 4; m++) {
            int c = 1536 + cb + 2 * ql;
            float v0 = bias[c], v1 = bias[c + 1];
            acc[m][0][0] = v0; acc[m][0][1] = v1;
            acc[m][0][2] = v0; acc[m][0][3] = v1;
        }

        uint32_t af0[4][4], af1[4][4];
        uint2 bs0, bs1;

        LOADB_SML(bs0, 0);
        LOADA(af0, 0);
        int kp = 0;
        while (true) {
            if (kp + 1 < KP) { LOADB_SML(bs1, kp + 1); LOADA(af1, kp + 1); }
            MMA_SML(af0, bs0);
            if (++kp >= KP) break;
            if (kp + 1 < KP) { LOADB_SML(bs0, kp + 1); LOADA(af0, kp + 1); }
            MMA_SML(af1, bs1);
            if (++kp >= KP) break;
        }

        size_t rb = (size_t)blockIdx.x * 64;
        int col = cb + 2 * ql;               // cols 0..127, valid < 100
        if (col < 100) {
            #pragma unroll
            for (int m = 0; m < 4; m++) {
                int r0 = m * 16 + gl;
                *(float2*)(out + (rb + r0)     * 100 + col) =
                    make_float2(acc[m][0][0], acc[m][0][1]);
                *(float2*)(out + (rb + r0 + 8) * 100 + col) =
                    make_float2(acc[m][0][2], acc[m][0][3]);
            }
        }
    }
}

// ---------------- launch ----------------------------------------------------
extern "C" void kernel_launch(void* const* d_in, const int* in_sizes, int n_in,
                              void* d_out, int out_size)
{
    const float* x   = (const float*)d_in[0];
    const float* mnv = (const float*)d_in[1];
    const float* mxv = (const float*)d_in[2];
    const float* pv  = (const float*)d_in[3];
    const float* kd  = (const float*)d_in[4];
    const float* qm  = (const float*)d_in[5];
    const float* qs  = (const float*)d_in[6];
    const float* km  = (const float*)d_in[7];
    const float* ks  = (const float*)d_in[8];
    const float* W1  = (const float*)d_in[9];
    const float* b1  = (const float*)d_in[10];
    const float* W2  = (const float*)d_in[11];
    const float* b2  = (const float*)d_in[12];
    const float* W3  = (const float*)d_in[13];
    const float* b3  = (const float*)d_in[14];
    const float* W4  = (const float*)d_in[15];
    const float* b4  = (const float*)d_in[16];

    cudaFuncSetAttribute(pivnet_main,
                         cudaFuncAttributeMaxDynamicSharedMemorySize, SMEM_BYTES);

    const int TOT = NBIG * BIG_H + 32 * SML_H;
    prep_weights<<<(TOT + 255) / 256, 256>>>(W1, W2, W3, W4);
    pivnet_main<<<8192, 512, SMEM_BYTES>>>(x, mnv, mxv, pv, kd, qm, qs, km, ks,
                                           b1, b2, b3, b4, (float*)d_out);
}

// round 17
// speedup vs baseline: 2.7010x; 1.0310x over previous
#include <cuda_runtime.h>
#include <cuda_fp16.h>
#include <cstdint>

// ---------------------------------------------------------------------------
// PivNet fused MLP, GB300 sm_103a (legacy mma.sync path; tcgen05 unavailable
// under the harness's compute_103 PTX target).
// R16: double-buffered activation slab (1 barrier/layer, no reader-wait),
// cross-layer B prefetch, L4 remapped to Gm=4 x Gn=4 (1 ldsm4/warp/piece).
// B fragments global->register (L2-resident packed image); A via ldmatrix.
// 512 threads / 16 warps (4/SMSP), single-fp16 weights, bias folded in acc.
// B=524288, DIM=4, GRID=16, K=100, H=512, FEAT=105 (padded to 128).
// Per CTA: 64 rows. L1-3: warp w owns cols [32w,32w+32).
// ---------------------------------------------------------------------------

#define NBIG      71            // big pieces (N=512): 7 (L1) + 32 (L2) + 32 (L3)
#define BIG_H     8192          // halves per big piece
#define SML_H     2048          // halves per small piece (L4, N=128), 32 pieces

// smem (halves): A0 [64][520] @0, A1 @33280, bias @66560 (1664 floats)
#define SLAB_H     33280
#define BIAS_OFF_H 66560
#define SMEM_BYTES 139776

__device__ __align__(16) __half g_wp[NBIG * BIG_H + 32 * SML_H];

__host__ __device__ __forceinline__ int phalf(int p) {
    return p < NBIG ? p * BIG_H : NBIG * BIG_H + (p - NBIG) * SML_H;
}

// ---------------- weight prep: fp32 -> fragment-packed fp16 ----------------
// Piece = [ntp][lane 32][4 b32 words]. Word w of lane l in nt-pair ntp is
// B col n = (ntp*2+(w>>1))*8 + (l>>2), k halves { 2*(l&3) + (w&1)*8, +1 }.
// One 16B load per lane = B fragments for 2 n8 tiles. (Validated R11-R15.)
__global__ void prep_weights(const float* __restrict__ W1, const float* __restrict__ W2,
                             const float* __restrict__ W3, const float* __restrict__ W4)
{
    int t = blockIdx.x * blockDim.x + threadIdx.x;
    const int TOT = NBIG * BIG_H + 32 * SML_H;
    if (t >= TOT) return;
    int p, i;
    if (t < NBIG * BIG_H) { p = t >> 13; i = t & (BIG_H - 1); }
    else { int u = t - NBIG * BIG_H; p = NBIG + (u >> 11); i = u & (SML_H - 1); }

    const float* W; int Kd, Nd, ld, k16;
    if (p < 7)       { W = W1; Kd = 105; Nd = 512; ld = 512; k16 = p;      }
    else if (p < 39) { W = W2; Kd = 512; Nd = 512; ld = 512; k16 = p - 7;  }
    else if (p < 71) { W = W3; Kd = 512; Nd = 512; ld = 512; k16 = p - 39; }
    else             { W = W4; Kd = 512; Nd = 100; ld = 100; k16 = p - 71; }

    int h    = i & 1;
    int w    = (i >> 1) & 3;
    int lane = (i >> 3) & 31;
    int ntp  = i >> 8;
    int n  = (ntp * 2 + (w >> 1)) * 8 + (lane >> 2);
    int kk = 2 * (lane & 3) + (w & 1) * 8 + h;
    int gk = k16 * 16 + kk;

    float wv = 0.0f;
    if (gk < Kd && n < Nd) wv = W[(size_t)gk * ld + n];
    g_wp[phalf(p) + i] = __float2half_rn(wv);
}

__device__ __forceinline__ void ldsm4(uint32_t* a, uint32_t addr) {
    asm volatile("ldmatrix.sync.aligned.m8n8.x4.shared.b16 {%0,%1,%2,%3}, [%4];"
                 : "=r"(a[0]), "=r"(a[1]), "=r"(a[2]), "=r"(a[3]) : "r"(addr));
}
__device__ __forceinline__ void mma16816(float* c, const uint32_t* a,
                                         uint32_t b0, uint32_t b1) {
    asm volatile(
        "mma.sync.aligned.m16n8k16.row.col.f32.f16.f16.f32 "
        "{%0,%1,%2,%3}, {%4,%5,%6,%7}, {%8,%9}, {%0,%1,%2,%3};"
        : "+f"(c[0]), "+f"(c[1]), "+f"(c[2]), "+f"(c[3])
        : "r"(a[0]), "r"(a[1]), "r"(a[2]), "r"(a[3]), "r"(b0), "r"(b1));
}

// fragment loads (wid/lane/gn/abase captured; weight base passed explicitly)
#define LOADB_BIG(BF, Wp, kpv) do {                                           \
    const __half* Wq_ = (Wp) + (size_t)(kpv) * BIG_H;                         \
    BF[0] = *(const uint4*)(Wq_ + ((wid * 2 + 0) * 32 + lane) * 8);           \
    BF[1] = *(const uint4*)(Wq_ + ((wid * 2 + 1) * 32 + lane) * 8);           \
} while (0)

#define LOADB_S(BF, Wp, kpv) do {                                             \
    const __half* Wq_ = (Wp) + (size_t)(kpv) * SML_H;                         \
    BF[0] = *(const uint4*)(Wq_ + ((gn * 2 + 0) * 32 + lane) * 8);            \
    BF[1] = *(const uint4*)(Wq_ + ((gn * 2 + 1) * 32 + lane) * 8);            \
} while (0)

#define LOADA(AF, kpv) do {                                                   \
    const uint32_t kb_ = (uint32_t)(kpv) * 32;                                \
    ldsm4(AF[0], abase + kb_);                                                \
    ldsm4(AF[1], abase + 16 * 1040 + kb_);                                    \
    ldsm4(AF[2], abase + 32 * 1040 + kb_);                                    \
    ldsm4(AF[3], abase + 48 * 1040 + kb_);                                    \
} while (0)

#define MMA_BIG(AF, BF) do {                                                  \
    _Pragma("unroll")                                                         \
    for (int m_ = 0; m_ < 4; m_++) mma16816(acc[m_][0], AF[m_], BF[0].x, BF[0].y); \
    _Pragma("unroll")                                                         \
    for (int m_ = 0; m_ < 4; m_++) mma16816(acc[m_][1], AF[m_], BF[0].z, BF[0].w); \
    _Pragma("unroll")                                                         \
    for (int m_ = 0; m_ < 4; m_++) mma16816(acc[m_][2], AF[m_], BF[1].x, BF[1].y); \
    _Pragma("unroll")                                                         \
    for (int m_ = 0; m_ < 4; m_++) mma16816(acc[m_][3], AF[m_], BF[1].z, BF[1].w); \
} while (0)

#define MMA_S(AF, BF) do {                                                    \
    mma16816(ac4[0], AF, BF[0].x, BF[0].y);                                   \
    mma16816(ac4[1], AF, BF[0].z, BF[0].w);                                   \
    mma16816(ac4[2], AF, BF[1].x, BF[1].y);                                   \
    mma16816(ac4[3], AF, BF[1].z, BF[1].w);                                   \
} while (0)

// ---------------- main fused kernel ----------------------------------------
__global__ void __launch_bounds__(512, 1)
pivnet_main(const float* __restrict__ x,   const float* __restrict__ mnv,
            const float* __restrict__ mxv,  const float* __restrict__ pivots,
            const float* __restrict__ knnd, const float* __restrict__ qm,
            const float* __restrict__ qs,   const float* __restrict__ km,
            const float* __restrict__ ks,   const float* __restrict__ b1,
            const float* __restrict__ b2,   const float* __restrict__ b3,
            const float* __restrict__ b4,   float* __restrict__ out)
{
    extern __shared__ __half smem[];
    __half* A0   = smem;                      // slab 0: [64][520]
    __half* A1   = smem + SLAB_H;             // slab 1
    float*  bias = (float*)(smem + BIAS_OFF_H);

    const int tid  = threadIdx.x;
    const int lane = tid & 31, wid = tid >> 5;   // 16 warps
    const int ql = lane & 3, gl = lane >> 2;
    const int gm = wid & 3, gn = wid >> 2;       // L4 mapping

    // ---- biases into smem ----
    {
        int i = tid;
        if (i < 512) { bias[i] = b1[i]; bias[512 + i] = b2[i]; bias[1024 + i] = b3[i]; }
        if (i < 128) bias[1536 + i] = (i < 100) ? b4[i] : 0.0f;
    }

    // ---- feature build into slab 0: 8 threads per row, 16 cols each ----
    {
        int row = tid >> 3, part = tid & 7;
        size_t gr = (size_t)blockIdx.x * 64 + row;
        float4 xv = *(const float4*)(x + gr * 4);
        float xa[4] = {xv.x, xv.y, xv.z, xv.w};
        float qn[4]; float diag2 = 0.0f; int idx = 0;
        #pragma unroll
        for (int d = 0; d < 4; d++) {
            float a = mnv[d], b = mxv[d];
            float bw = (b - a) * 0.0625f;
            diag2 += bw * bw;
            float s = (xa[d] - a) / (b - a) * 16.0f;
            int bi = (int)floorf(s);
            bi = min(max(bi, 0), 15);
            idx = idx * 16 + bi;
            qn[d] = (xa[d] - qm[d]) / qs[d];
        }
        float4 pv = *(const float4*)(pivots + (size_t)idx * 4);
        float dd = (xa[0]-pv.x)*(xa[0]-pv.x) + (xa[1]-pv.y)*(xa[1]-pv.y)
                 + (xa[2]-pv.z)*(xa[2]-pv.z) + (xa[3]-pv.w)*(xa[3]-pv.w);
        float dist = sqrtf(dd) * rsqrtf(diag2);
        const float* kr = knnd + (size_t)idx * 100;
        __half* Ar = A0 + row * 520;
        for (int c = part * 16; c < part * 16 + 16; c++) {
            float v;
            if (c < 4)        v = qn[c];
            else if (c == 4)  v = dist;
            else if (c < 105) v = (kr[c - 5] - km[c - 5]) / ks[c - 5];
            else              v = 0.0f;
            Ar[c] = __float2half_rn(v);
        }
    }

    // ldmatrix per-thread offset (bytes) within a slab
    const uint32_t As0 = (uint32_t)__cvta_generic_to_shared(A0);
    const int rowa = (lane & 7) + ((lane >> 3) & 1) * 8;
    const int kadd = ((lane >> 4) & 1) * 8;
    const uint32_t aoff = (uint32_t)(rowa * 520 + kadd) * 2;

    float acc[4][4][4];
    uint32_t af0[4][4], af1[4][4];
    uint4 bf0[2], bf1[2], bs0[2], bs1[2];

    // preload B for layer 0 piece 0 (independent of A), then publish A0
    LOADB_BIG(bf0, g_wp, 0);
    __syncthreads();

    // ================= layers 1-3 (N=512) =================
    int pbase = 0;
    for (int L = 0; L < 3; L++) {
        const int KP = (L == 0) ? 7 : 32;
        const int cb = wid * 32;
        const __half* gW = g_wp + (size_t)pbase * BIG_H;
        const uint32_t abase = As0 + (uint32_t)(L & 1) * (SLAB_H * 2) + aoff;
        __half* An = (L & 1) ? A0 : A1;      // epilogue target = other slab

        #pragma unroll
        for (int m = 0; m < 4; m++)
            #pragma unroll
            for (int nt = 0; nt < 4; nt++) {
                int c = L * 512 + cb + nt * 8 + 2 * ql;
                float v0 = bias[c], v1 = bias[c + 1];
                acc[m][nt][0] = v0; acc[m][nt][1] = v1;
                acc[m][nt][2] = v0; acc[m][nt][3] = v1;
            }

        LOADA(af0, 0);                       // bf0 was preloaded pre-barrier
        int kp = 0;
        while (true) {
            if (kp + 1 < KP) { LOADB_BIG(bf1, gW, kp + 1); LOADA(af1, kp + 1); }
            MMA_BIG(af0, bf0);
            if (++kp >= KP) break;
            if (kp + 1 < KP) { LOADB_BIG(bf0, gW, kp + 1); LOADA(af0, kp + 1); }
            MMA_BIG(af1, bf1);
            if (++kp >= KP) break;
        }
        pbase += KP;

        // epilogue -> other slab (no reader-wait barrier needed)
        #pragma unroll
        for (int m = 0; m < 4; m++)
            #pragma unroll
            for (int nt = 0; nt < 4; nt++) {
                int col = cb + nt * 8 + 2 * ql;
                int r0  = m * 16 + gl;
                float v00 = fmaxf(acc[m][nt][0], 0.0f);
                float v01 = fmaxf(acc[m][nt][1], 0.0f);
                float v10 = fmaxf(acc[m][nt][2], 0.0f);
                float v11 = fmaxf(acc[m][nt][3], 0.0f);
                *(__half2*)(An + r0 * 520 + col)       = __floats2half2_rn(v00, v01);
                *(__half2*)(An + (r0 + 8) * 520 + col) = __floats2half2_rn(v10, v11);
            }

        // cross-layer B prefetch (A-independent) before the publish barrier
        if (L < 2) LOADB_BIG(bf0, g_wp + (size_t)pbase * BIG_H, 0);
        else       LOADB_S(bs0, g_wp + (size_t)NBIG * BIG_H, 0);
        __syncthreads();                     // publish new slab
    }

    // ================= layer 4 (N=100 -> 128), Gm=4 x Gn=4 =================
    {
        const int KP = 32;
        const __half* gW4 = g_wp + (size_t)NBIG * BIG_H;
        const uint32_t abase3 = As0 + (SLAB_H * 2) + aoff
                              + (uint32_t)(gm * 16) * 1040;  // slab 1, m-tile gm

        float ac4[4][4];
        #pragma unroll
        for (int nt = 0; nt < 4; nt++) {
            int c = 1536 + gn * 32 + nt * 8 + 2 * ql;
            float v0 = bias[c], v1 = bias[c + 1];
            ac4[nt][0] = v0; ac4[nt][1] = v1;
            ac4[nt][2] = v0; ac4[nt][3] = v1;
        }

        uint32_t a0[4], a1[4];
        ldsm4(a0, abase3);                   // bs0 preloaded pre-barrier
        int kp = 0;
        while (true) {
            if (kp + 1 < KP) { LOADB_S(bs1, gW4, kp + 1); ldsm4(a1, abase3 + (uint32_t)(kp + 1) * 32); }
            MMA_S(a0, bs0);
            if (++kp >= KP) break;
            if (kp + 1 < KP) { LOADB_S(bs0, gW4, kp + 1); ldsm4(a0, abase3 + (uint32_t)(kp + 1) * 32); }
            MMA_S(a1, bs1);
            if (++kp >= KP) break;
        }

        size_t rb = (size_t)blockIdx.x * 64;
        #pragma unroll
        for (int nt = 0; nt < 4; nt++) {
            int col = gn * 32 + nt * 8 + 2 * ql;
            if (col < 100) {
                int r0 = gm * 16 + gl;
                *(float2*)(out + (rb + r0)     * 100 + col) = make_float2(ac4[nt][0], ac4[nt][1]);
                *(float2*)(out + (rb + r0 + 8) * 100 + col) = make_float2(ac4[nt][2], ac4[nt][3]);
            }
        }
    }
}

// ---------------- launch ----------------------------------------------------
extern "C" void kernel_launch(void* const* d_in, const int* in_sizes, int n_in,
                              void* d_out, int out_size)
{
    const float* x   = (const float*)d_in[0];
    const float* mnv = (const float*)d_in[1];
    const float* mxv = (const float*)d_in[2];
    const float* pv  = (const float*)d_in[3];
    const float* kd  = (const float*)d_in[4];
    const float* qm  = (const float*)d_in[5];
    const float* qs  = (const float*)d_in[6];
    const float* km  = (const float*)d_in[7];
    const float* ks  = (const float*)d_in[8];
    const float* W1  = (const float*)d_in[9];
    const float* b1  = (const float*)d_in[10];
    const float* W2  = (const float*)d_in[11];
    const float* b2  = (const float*)d_in[12];
    const float* W3  = (const float*)d_in[13];
    const float* b3  = (const float*)d_in[14];
    const float* W4  = (const float*)d_in[15];
    const float* b4  = (const float*)d_in[16];

    cudaFuncSetAttribute(pivnet_main,
                         cudaFuncAttributeMaxDynamicSharedMemorySize, SMEM_BYTES);

    const int TOT = NBIG * BIG_H + 32 * SML_H;
    prep_weights<<<(TOT + 255) / 256, 256>>>(W1, W2, W3, W4);
    pivnet_main<<<8192, 512, SMEM_BYTES>>>(x, mnv, mxv, pv, kd, qm, qs, km, ks,
                                           b1, b2, b3, b4, (float*)d_out);
}